// round 1
// baseline (speedup 1.0000x reference)
#include <cuda_runtime.h>

// Locally-connected 3x3 "conv" with unshared per-position weights.
// out[b,i,j] = 9 * sum_{m,n} x[b,i+m,j+n] * w[i,j,m*3+n] + sum_k b[i,j,k]
// x zero-padded on the high side in both spatial dims.

#define Bn 64
#define Wd 256
#define Hd 256
#define UNITS 9
#define BG 4              // batch groups (per-row blocks)
#define BPG (Bn / BG)     // 16 batches per group

__global__ __launch_bounds__(256, 8)
void lc_kernel(const float* __restrict__ x,
               const float* __restrict__ w,
               const float* __restrict__ b,
               float* __restrict__ out) {
    // 3 input rows with 8-float pad (cols 256,257 are the zero halo; stride 264
    // keeps float4 stores 16B-aligned and LDS conflict-free).
    __shared__ float xs[3][Hd + 8];
    __shared__ float ws[Hd * UNITS];   // 2304 floats: w row for output row i

    const int j = threadIdx.x;         // output column
    const int i = blockIdx.y;          // output row
    const int g = blockIdx.x;          // batch group

    // ---- stage w row into SMEM (fully coalesced, once per block) ----
    const float* wrow = w + (size_t)i * Hd * UNITS;
    #pragma unroll
    for (int t = 0; t < UNITS; t++)
        ws[t * 256 + j] = wrow[t * 256 + j];

    // ---- per-thread bias sum (once per block; 9 strided LDG, negligible) ----
    const float* brow = b + (size_t)i * Hd * UNITS;
    float sb = 0.f;
    #pragma unroll
    for (int k = 0; k < UNITS; k++)
        sb += brow[j * UNITS + k];

    // ---- zero the 2-column halo (6 writes) ----
    if (j < 6) {
        int m = j >> 1;
        xs[m][Hd + (j & 1)] = 0.f;
    }
    __syncthreads();

    // per-thread weights -> registers. ws[j*9+k]: 9 coprime 32 => conflict-free.
    float wreg[UNITS];
    #pragma unroll
    for (int k = 0; k < UNITS; k++)
        wreg[k] = ws[j * UNITS + k];

    for (int bi = 0; bi < BPG; bi++) {
        const int bb = g * BPG + bi;

        __syncthreads();   // protect xs from previous iteration's readers

        // load 3 input rows (float4, 192 threads). Rows >= Wd are zero pad.
        if (j < 192) {
            const int m = j >> 6;      // 0..2
            const int q = j & 63;      // 0..63 -> float4 index
            const int r = i + m;
            float4 v = make_float4(0.f, 0.f, 0.f, 0.f);
            if (r < Wd)
                v = *reinterpret_cast<const float4*>(
                        x + ((size_t)bb * Wd + r) * Hd + q * 4);
            *reinterpret_cast<float4*>(&xs[m][q * 4]) = v;
        }
        __syncthreads();

        float acc = 0.f;
        #pragma unroll
        for (int m = 0; m < 3; m++)
            #pragma unroll
            for (int n = 0; n < 3; n++)
                acc = fmaf(xs[m][j + n], wreg[m * 3 + n], acc);

        out[((size_t)bb * Wd + i) * Hd + j] = 9.0f * acc + sb;
    }
}

extern "C" void kernel_launch(void* const* d_in, const int* in_sizes, int n_in,
                              void* d_out, int out_size) {
    const float* x   = (const float*)d_in[0];
    const float* w   = (const float*)d_in[1];
    const float* b   = (const float*)d_in[2];
    float*       out = (float*)d_out;

    dim3 grid(BG, Wd);
    lc_kernel<<<grid, 256>>>(x, w, b, out);
}

// round 2
// speedup vs baseline: 1.4212x; 1.4212x over previous
#include <cuda_runtime.h>

// Locally-connected 3x3 conv, unshared weights:
// out[b,i,j] = 9 * sum_{m,n} x[b,i+m,j+n] * w[i,j,3m+n] + sum_k b[i,j,k]
// x zero-padded on the high side of both spatial dims.
//
// Block = 256 threads = jt(16 col-pairs) x ii(4 rows) x bq(4 batch quarters).
// Grid  = (8 col-tiles of 32, 64 row-tiles of 4) = 512 blocks, single wave.
// No smem for x, no barriers in the hot loop; weights register-resident.

#define Wd 256
#define Hd 256
#define Bn 64

__global__ __launch_bounds__(256, 4)
void lc_kernel(const float* __restrict__ x,
               const float* __restrict__ w,
               const float* __restrict__ bvec,
               float* __restrict__ out) {
    __shared__ float ws[1152];   // 4 rows x 32 cols x 9
    __shared__ float bs[1152];

    const int t  = threadIdx.x;
    const int jt = t & 15;          // 0..15 : column pair
    const int ii = (t >> 4) & 3;    // 0..3  : row within tile
    const int bq = t >> 6;          // 0..3  : batch quarter

    const int i0 = blockIdx.y * 4;
    const int j0 = blockIdx.x * 32;
    const int i  = i0 + ii;
    const int j  = j0 + jt * 2;

    // ---- stage w/b tile into smem (coalesced), once per block ----
    for (int idx = t; idx < 1152; idx += 256) {
        int r    = idx / 288;            // row within tile
        int rest = idx - r * 288;        // 32 cols * 9 units
        size_t g = ((size_t)(i0 + r) * Hd + j0) * 9 + rest;
        ws[idx] = w[g];
        bs[idx] = bvec[g];
    }
    __syncthreads();

    // ---- per-thread weights (2 columns x 9) and bias sums -> registers ----
    float wr[2][9];
    float bsum[2];
    #pragma unroll
    for (int c = 0; c < 2; c++) {
        const float* pw = &ws[(ii * 32 + jt * 2 + c) * 9];
        const float* pb = &bs[(ii * 32 + jt * 2 + c) * 9];
        float s = 0.f;
        #pragma unroll
        for (int k = 0; k < 9; k++) { wr[c][k] = pw[k]; s += pb[k]; }
        bsum[c] = s;
    }

    const bool qok  = (j + 2 < Hd);     // cols j+2, j+3 exist
    const bool r1ok = (i + 1 < Wd);
    const bool r2ok = (i + 2 < Wd);

    const float2 z2 = make_float2(0.f, 0.f);

    size_t xoff = (size_t)(bq * 16) * (Wd * Hd) + (size_t)i * Hd + j;
    float* op   = out + xoff;

    #pragma unroll 2
    for (int bi = 0; bi < 16; bi++) {
        const float* xb = x + xoff;

        float2 p0, q0, p1, q1, p2, q2;
        p0 = *(const float2*)xb;
        q0 = qok ? *(const float2*)(xb + 2) : z2;
        if (r1ok) {
            p1 = *(const float2*)(xb + Hd);
            q1 = qok ? *(const float2*)(xb + Hd + 2) : z2;
        } else { p1 = z2; q1 = z2; }
        if (r2ok) {
            p2 = *(const float2*)(xb + 2 * Hd);
            q2 = qok ? *(const float2*)(xb + 2 * Hd + 2) : z2;
        } else { p2 = z2; q2 = z2; }

        float a0 = p0.x * wr[0][0];
        a0 = fmaf(p0.y, wr[0][1], a0);
        a0 = fmaf(q0.x, wr[0][2], a0);
        a0 = fmaf(p1.x, wr[0][3], a0);
        a0 = fmaf(p1.y, wr[0][4], a0);
        a0 = fmaf(q1.x, wr[0][5], a0);
        a0 = fmaf(p2.x, wr[0][6], a0);
        a0 = fmaf(p2.y, wr[0][7], a0);
        a0 = fmaf(q2.x, wr[0][8], a0);

        float a1 = p0.y * wr[1][0];
        a1 = fmaf(q0.x, wr[1][1], a1);
        a1 = fmaf(q0.y, wr[1][2], a1);
        a1 = fmaf(p1.y, wr[1][3], a1);
        a1 = fmaf(q1.x, wr[1][4], a1);
        a1 = fmaf(q1.y, wr[1][5], a1);
        a1 = fmaf(p2.y, wr[1][6], a1);
        a1 = fmaf(q2.x, wr[1][7], a1);
        a1 = fmaf(q2.y, wr[1][8], a1);

        *(float2*)op = make_float2(fmaf(9.f, a0, bsum[0]),
                                   fmaf(9.f, a1, bsum[1]));

        xoff += (size_t)Wd * Hd;
        op   += (size_t)Wd * Hd;
    }
}

extern "C" void kernel_launch(void* const* d_in, const int* in_sizes, int n_in,
                              void* d_out, int out_size) {
    const float* x   = (const float*)d_in[0];
    const float* w   = (const float*)d_in[1];
    const float* b   = (const float*)d_in[2];
    float*       out = (float*)d_out;

    dim3 grid(8, 64);   // (j-tiles of 32, i-tiles of 4)
    lc_kernel<<<grid, 256>>>(x, w, b, out);
}